// round 15
// baseline (speedup 1.0000x reference)
#include <cuda_runtime.h>
#include <cstdint>

#define NTOK   4096
#define DMODEL 2048
#define NH     16
#define HDIM   128
#define SDIM   64
#define NSLOT  16
#define NUNIT  (NTOK * NH)

#define OUT_STACK_OFF 8388608ll
#define OUT_MASK_OFF  75497472ll

#define KST_SMEM 65536   // dynamic: old4 (32KB) + new4 (32KB)

__device__ float g_part[8ll * NTOK * 48];
__device__ float g_act[(size_t)NTOK * 48];
__device__ float g_k[(size_t)NUNIT * SDIM];
__device__ float g_mo[(size_t)NUNIT * SDIM];

__device__ __forceinline__ uint32_t smem_u32(const void* p) {
    uint32_t a;
    asm("{ .reg .u64 t; cvta.to.shared.u64 t, %1; cvt.u32.u64 %0, t; }"
        : "=r"(a) : "l"(p));
    return a;
}

// ---- logits body: split-K 8, 64-tok tile, pad 66 (conflict-free float2 LDS).
__device__ __forceinline__ void logits_body(float* sm,
                                            const float* __restrict__ hid,
                                            const float* __restrict__ Wa,
                                            int blk) {
    float* a_sm = sm;            // 64 x 66
    float* w_sm = sm + 64 * 66;  // 48 x 66
    const int tile = blk >> 3;
    const int ks   = blk & 7;
    const int t0   = tile * 64;
    const int kb   = ks * 256;
    const int tid = threadIdx.x;
    const int tg  = tid & 15;
    const int og  = tid >> 4;
    float acc[4][3];
#pragma unroll
    for (int i = 0; i < 4; i++)
#pragma unroll
        for (int j = 0; j < 3; j++) acc[i][j] = 0.f;

    for (int kc = 0; kc < 256; kc += 64) {
        __syncthreads();
        for (int i = tid; i < 64 * 32; i += 256) {
            int t = i >> 5, c2 = (i & 31) << 1;
            *(float2*)&a_sm[t * 66 + c2] =
                *(const float2*)&hid[(size_t)(t0 + t) * DMODEL + kb + kc + c2];
        }
        for (int i = tid; i < 48 * 32; i += 256) {
            int o = i >> 5, c2 = (i & 31) << 1;
            *(float2*)&w_sm[o * 66 + c2] =
                *(const float2*)&Wa[(size_t)o * DMODEL + kb + kc + c2];
        }
        __syncthreads();
#pragma unroll
        for (int kk = 0; kk < 64; kk += 2) {
            float2 av[4], wv[3];
#pragma unroll
            for (int tt = 0; tt < 4; tt++)
                av[tt] = *(const float2*)&a_sm[(tg + 16 * tt) * 66 + kk];
#pragma unroll
            for (int oc = 0; oc < 3; oc++)
                wv[oc] = *(const float2*)&w_sm[(og * 3 + oc) * 66 + kk];
#pragma unroll
            for (int tt = 0; tt < 4; tt++)
#pragma unroll
                for (int oc = 0; oc < 3; oc++) {
                    acc[tt][oc] = fmaf(av[tt].x, wv[oc].x, acc[tt][oc]);
                    acc[tt][oc] = fmaf(av[tt].y, wv[oc].y, acc[tt][oc]);
                }
        }
    }
#pragma unroll
    for (int tt = 0; tt < 4; tt++)
#pragma unroll
        for (int oc = 0; oc < 3; oc++)
            g_part[((size_t)ks * NTOK + t0 + tg + 16 * tt) * 48 + og * 3 + oc] =
                acc[tt][oc];
}

// ---- down body: 128x64 tile, pad 34 (conflict-free float2 LDS).
__device__ __forceinline__ void down_body(float* sm,
                                          const float* __restrict__ hid,
                                          const float* __restrict__ Wd,
                                          int blk) {
    float* a_sm = sm;             // 128 x 34
    float* w_sm = sm + 128 * 34;  // 64 x 34
    const int u0 = blk * 128;
    const int tid = threadIdx.x;
    const int rg = tid & 15;
    const int cg = tid >> 4;
    float acc[8][4];
#pragma unroll
    for (int i = 0; i < 8; i++)
#pragma unroll
        for (int j = 0; j < 4; j++) acc[i][j] = 0.f;

    for (int kc = 0; kc < 128; kc += 32) {
        __syncthreads();
        for (int i = tid; i < 128 * 16; i += 256) {
            int r = i >> 4, c2 = (i & 15) << 1;
            *(float2*)&a_sm[r * 34 + c2] =
                *(const float2*)&hid[(size_t)(u0 + r) * HDIM + kc + c2];
        }
        for (int i = tid; i < 64 * 16; i += 256) {
            int c = i >> 4, c2 = (i & 15) << 1;
            *(float2*)&w_sm[c * 34 + c2] =
                *(const float2*)&Wd[(size_t)c * HDIM + kc + c2];
        }
        __syncthreads();
#pragma unroll
        for (int kk = 0; kk < 32; kk += 2) {
            float2 av[8], wv[4];
#pragma unroll
            for (int rr = 0; rr < 8; rr++)
                av[rr] = *(const float2*)&a_sm[(rg + 16 * rr) * 34 + kk];
#pragma unroll
            for (int cc = 0; cc < 4; cc++)
                wv[cc] = *(const float2*)&w_sm[(cg * 4 + cc) * 34 + kk];
#pragma unroll
            for (int rr = 0; rr < 8; rr++)
#pragma unroll
                for (int cc = 0; cc < 4; cc++) {
                    acc[rr][cc] = fmaf(av[rr].x, wv[cc].x, acc[rr][cc]);
                    acc[rr][cc] = fmaf(av[rr].y, wv[cc].y, acc[rr][cc]);
                }
        }
    }
#pragma unroll
    for (int rr = 0; rr < 8; rr++) {
        float4 v = make_float4(acc[rr][0], acc[rr][1], acc[rr][2], acc[rr][3]);
        *(float4*)&g_k[(size_t)(u0 + rg + 16 * rr) * SDIM + cg * 4] = v;
    }
}

// ---- Kernel 1: merged logits + down, reg-capped for 3 blocks/SM.
__global__ void __launch_bounds__(256, 3) k_proj(const float* __restrict__ hid,
                                                 const float* __restrict__ Wa,
                                                 const float* __restrict__ Wd) {
    __shared__ float sm[64 * 66 + 48 * 66];   // >= 128*34 + 64*34
    if (blockIdx.x < 512) logits_body(sm, hid, Wa, blockIdx.x);
    else                  down_body(sm, hid, Wd, blockIdx.x - 512);
}

// ---- Kernel 2: reduce partials, softmax over 3 actions.
__global__ void __launch_bounds__(256) k_actsm() {
    const int gid = blockIdx.x * 256 + threadIdx.x;
    const int t = gid >> 4, h = gid & 15;
    float l0 = 0.f, l1 = 0.f, l2 = 0.f;
#pragma unroll
    for (int ks = 0; ks < 8; ks++) {
        size_t b = ((size_t)ks * NTOK + t) * 48 + h * 3;
        l0 += g_part[b]; l1 += g_part[b + 1]; l2 += g_part[b + 2];
    }
    const float s = 0.08838834764831845f;
    l0 *= s; l1 *= s; l2 *= s;
    float m = fmaxf(l0, fmaxf(l1, l2));
    float e0 = __expf(l0 - m), e1 = __expf(l1 - m), e2 = __expf(l2 - m);
    float inv = 1.f / (e0 + e1 + e2);
    size_t ob = (size_t)t * 48 + h * 3;
    g_act[ob] = e0 * inv; g_act[ob + 1] = e1 * inv; g_act[ob + 2] = e2 * inv;
}

// ---- Kernel 3: stack blend, 8 units/block, 32KB TMA in/out, coef trick.
__global__ void __launch_bounds__(256) k_stack(const float* __restrict__ stk,
                                               const float* __restrict__ msk,
                                               const float* __restrict__ Wg,
                                               float* __restrict__ out) {
    extern __shared__ float4 dyn4[];
    float4* old4 = dyn4;             // [8][256]
    float4* new4 = dyn4 + 2048;      // [8][256]
    __shared__ alignas(8) unsigned long long mbar;
    __shared__ float4 ksm4[128];     // [unit][dv]
    __shared__ float red[8][17];
    __shared__ float coef[8][17];
    __shared__ float msm[128];
    __shared__ float acts[24];
    const int tid  = threadIdx.x;
    const int slot = tid >> 4;
    const int dv   = tid & 15;
    const int u0   = blockIdx.x * 8;

    const uint32_t mb = smem_u32(&mbar);
    if (tid == 0) {
        asm volatile("mbarrier.init.shared.b64 [%0], 1;" :: "r"(mb) : "memory");
        asm volatile("fence.proxy.async.shared::cta;" ::: "memory");
    }
    __syncthreads();
    if (tid == 0) {
        asm volatile("mbarrier.arrive.expect_tx.shared.b64 _, [%0], 32768;"
                     :: "r"(mb) : "memory");
        asm volatile(
            "cp.async.bulk.shared::cluster.global.mbarrier::complete_tx::bytes "
            "[%0], [%1], 32768, [%2];"
            :: "r"(smem_u32(old4)),
               "l"(stk + (size_t)u0 * 1024), "r"(mb) : "memory");
    }

    const float4 g4 = ((const float4*)Wg)[dv];
    if (tid < 128) msm[tid] = msk[(size_t)u0 * 16 + tid];
    if (tid < 24) {
        int i = tid / 3, c = tid - i * 3;
        int u = u0 + i;
        acts[tid] = g_act[(size_t)(u >> 4) * 48 + (u & 15) * 3 + c];
    }
    if (tid < 128) {
        float4 kv = ((const float4*)g_k)[(size_t)u0 * 16 + tid];
        ksm4[tid] = kv;
        float p = kv.x * g4.x + kv.y * g4.y + kv.z * g4.z + kv.w * g4.w;
        p += __shfl_xor_sync(0xffffffffu, p, 8);
        p += __shfl_xor_sync(0xffffffffu, p, 4);
        p += __shfl_xor_sync(0xffffffffu, p, 2);
        p += __shfl_xor_sync(0xffffffffu, p, 1);
        if ((tid & 15) == 0) red[tid >> 4][16] = p;
    }

    {
        uint32_t done;
        asm volatile(
            "{\n\t.reg .pred p;\n\t"
            "WAITLP:\n\t"
            "mbarrier.try_wait.parity.shared.b64 p, [%1], 0, 0x989680;\n\t"
            "selp.b32 %0, 1, 0, p;\n\t"
            "@!p bra WAITLP;\n\t}"
            : "=r"(done) : "r"(mb) : "memory");
    }

    float4 r4[8];
#pragma unroll
    for (int i = 0; i < 8; i++) {
        r4[i] = old4[i * 256 + tid];
        float p = r4[i].x * g4.x + r4[i].y * g4.y + r4[i].z * g4.z + r4[i].w * g4.w;
        p += __shfl_xor_sync(0xffffffffu, p, 8);
        p += __shfl_xor_sync(0xffffffffu, p, 4);
        p += __shfl_xor_sync(0xffffffffu, p, 2);
        p += __shfl_xor_sync(0xffffffffu, p, 1);
        if (dv == 0) red[i][slot] = p;
    }
    __syncthreads();   // red, ksm4, msm, acts ready

#pragma unroll
    for (int i = 0; i < 8; i++) {
        float ap = acts[i * 3], apop = acts[i * 3 + 1], an = acts[i * 3 + 2];
        float4 prev = (slot == 0) ? ksm4[i * 16 + dv] : old4[i * 256 + tid - 16];
        float4 nxt  = (slot == 15) ? make_float4(0.f, 0.f, 0.f, 0.f)
                                   : old4[i * 256 + tid + 16];
        float4 c = r4[i];
        float4 nw;
        nw.x = ap * prev.x + apop * nxt.x + an * c.x;
        nw.y = ap * prev.y + apop * nxt.y + an * c.y;
        nw.z = ap * prev.z + apop * nxt.z + an * c.z;
        nw.w = ap * prev.w + apop * nxt.w + an * c.w;
        new4[i * 256 + tid] = nw;
    }

    if (tid < 128) {
        const int q2 = tid >> 4, j = tid & 15;
        float ap = acts[q2 * 3], apop = acts[q2 * 3 + 1], an = acts[q2 * 3 + 2];
        float pm = (j == 0) ? 1.f : msm[q2 * 16 + j - 1];
        float qm = (j < 15) ? msm[q2 * 16 + j + 1] : 0.f;
        out[OUT_MASK_OFF + (size_t)u0 * 16 + tid] =
            ap * pm + apop * qm + an * msm[q2 * 16 + j];
    }

    {
        const int q = tid >> 5;
        const int j = tid & 15;
        const int lane = tid & 31;
        float ap = acts[q * 3], apop = acts[q * 3 + 1], an = acts[q * 3 + 2];
        float pm = (j == 0) ? 1.f : msm[q * 16 + j - 1];
        float qm = (j < 15) ? msm[q * 16 + j + 1] : 0.f;
        float mk = ap * pm + apop * qm + an * msm[q * 16 + j];
        float Sm1 = (j == 0) ? red[q][16] : red[q][j - 1];
        float Sp1 = (j < 15) ? red[q][j + 1] : 0.f;
        float v = ap * Sm1 + apop * Sp1 + an * red[q][j] + (1.f - mk) * (-1e9f);
        float mx = v;
        mx = fmaxf(mx, __shfl_xor_sync(0xffffffffu, mx, 8));
        mx = fmaxf(mx, __shfl_xor_sync(0xffffffffu, mx, 4));
        mx = fmaxf(mx, __shfl_xor_sync(0xffffffffu, mx, 2));
        mx = fmaxf(mx, __shfl_xor_sync(0xffffffffu, mx, 1));
        float e = __expf(v - mx);
        float ss = e;
        ss += __shfl_xor_sync(0xffffffffu, ss, 8);
        ss += __shfl_xor_sync(0xffffffffu, ss, 4);
        ss += __shfl_xor_sync(0xffffffffu, ss, 2);
        ss += __shfl_xor_sync(0xffffffffu, ss, 1);
        float wgt = e / ss;
        float wp1 = __shfl_down_sync(0xffffffffu, wgt, 1);
        if (j == 15) wp1 = 0.f;
        float wm1 = __shfl_up_sync(0xffffffffu, wgt, 1);
        if (j == 0) wm1 = 0.f;
        if (lane < 16) {
            coef[q][j] = ap * wp1 + apop * wm1 + an * wgt;
            if (lane == 0) coef[q][16] = ap * wgt;
        }
    }
    __syncthreads();   // new4 + coef ready

    if (tid == 0) {
        asm volatile("fence.proxy.async.shared::cta;" ::: "memory");
        asm volatile(
            "cp.async.bulk.global.shared::cta.bulk_group [%0], [%1], 32768;"
            :: "l"(out + OUT_STACK_OFF + (size_t)u0 * 1024),
               "r"(smem_u32(new4)) : "memory");
        asm volatile("cp.async.bulk.commit_group;" ::: "memory");
    }

    {
        const int q = tid >> 5, d0 = tid & 31;
        const float* s  = (const float*)old4 + q * 1024;
        const float* ks = (const float*)ksm4 + q * 64;
#pragma unroll
        for (int dd = 0; dd < 2; dd++) {
            const int d = d0 + 32 * dd;
            float mo = coef[q][16] * ks[d];
#pragma unroll
            for (int m = 0; m < 16; m++) mo = fmaf(coef[q][m], s[m * 64 + d], mo);
            g_mo[(size_t)(u0 + q) * 64 + d] = mo;
        }
    }

    if (tid == 0)
        asm volatile("cp.async.bulk.wait_group 0;" ::: "memory");
}

// ---- Kernel 4: out = res_weight * (mo @ W_up^T) + hidden. Pad 66 conflict-free.
__global__ void __launch_bounds__(256, 3) k_up(const float* __restrict__ hid,
                                               const float* __restrict__ Wu,
                                               const float* __restrict__ rsw,
                                               float* __restrict__ out) {
    const int u0 = blockIdx.x * 64;
    __shared__ float a_sm[64 * 66];    // 64 rows x K=64 (pad 66)
    __shared__ float w_sm[128 * 66];   // 128 cols x K=64 (pad 66)
    const int tid = threadIdx.x;
    const int rg = tid & 15;           // rows rg + 16*rr (rr<4)
    const int cg = tid >> 4;           // cols cg*8 .. cg*8+7

    for (int i = tid; i < 64 * 32; i += 256) {
        int r = i >> 5, c2 = (i & 31) << 1;
        *(float2*)&a_sm[r * 66 + c2] =
            *(const float2*)&g_mo[(size_t)(u0 + r) * SDIM + c2];
    }
    for (int i = tid; i < 128 * 32; i += 256) {
        int c = i >> 5, c2 = (i & 31) << 1;
        *(float2*)&w_sm[c * 66 + c2] =
            *(const float2*)&Wu[(size_t)c * SDIM + c2];
    }
    __syncthreads();

    float acc[4][8];
#pragma unroll
    for (int i = 0; i < 4; i++)
#pragma unroll
        for (int j = 0; j < 8; j++) acc[i][j] = 0.f;

#pragma unroll 4
    for (int kk = 0; kk < 64; kk += 2) {
        float2 av[4], wv[8];
#pragma unroll
        for (int rr = 0; rr < 4; rr++)
            av[rr] = *(const float2*)&a_sm[(rg + 16 * rr) * 66 + kk];
#pragma unroll
        for (int cc = 0; cc < 8; cc++)
            wv[cc] = *(const float2*)&w_sm[(cg * 8 + cc) * 66 + kk];
#pragma unroll
        for (int rr = 0; rr < 4; rr++)
#pragma unroll
            for (int cc = 0; cc < 8; cc++) {
                acc[rr][cc] = fmaf(av[rr].x, wv[cc].x, acc[rr][cc]);
                acc[rr][cc] = fmaf(av[rr].y, wv[cc].y, acc[rr][cc]);
            }
    }

    const float rw = rsw[0];
#pragma unroll
    for (int rr = 0; rr < 4; rr++) {
        size_t b = (size_t)(u0 + rg + 16 * rr) * HDIM + cg * 8;
        float4 h0 = *(const float4*)&hid[b];
        float4 h1 = *(const float4*)&hid[b + 4];
        float4 o0 = make_float4(fmaf(rw, acc[rr][0], h0.x), fmaf(rw, acc[rr][1], h0.y),
                                fmaf(rw, acc[rr][2], h0.z), fmaf(rw, acc[rr][3], h0.w));
        float4 o1 = make_float4(fmaf(rw, acc[rr][4], h1.x), fmaf(rw, acc[rr][5], h1.y),
                                fmaf(rw, acc[rr][6], h1.z), fmaf(rw, acc[rr][7], h1.w));
        *(float4*)&out[b] = o0;
        *(float4*)&out[b + 4] = o1;
    }
}

extern "C" void kernel_launch(void* const* d_in, const int* in_sizes, int n_in,
                              void* d_out, int out_size) {
    const float* hid = (const float*)d_in[0];
    const float* stk = (const float*)d_in[1];
    const float* msk = (const float*)d_in[2];
    const float* Wa  = (const float*)d_in[3];
    const float* Wg  = (const float*)d_in[4];
    const float* Wd  = (const float*)d_in[5];
    const float* Wu  = (const float*)d_in[6];
    const float* rsw = (const float*)d_in[7];
    float* out = (float*)d_out;

    cudaFuncSetAttribute(k_stack, cudaFuncAttributeMaxDynamicSharedMemorySize,
                         KST_SMEM);

    k_proj<<<1024, 256>>>(hid, Wa, Wd);
    k_actsm<<<256, 256>>>();
    k_stack<<<8192, 256, KST_SMEM>>>(stk, msk, Wg, out);
    k_up<<<1024, 256>>>(hid, Wu, rsw, out);
}

// round 16
// speedup vs baseline: 1.0532x; 1.0532x over previous
#include <cuda_runtime.h>
#include <cstdint>

#define NTOK   4096
#define DMODEL 2048
#define NH     16
#define HDIM   128
#define SDIM   64
#define NSLOT  16
#define NUNIT  (NTOK * NH)

#define OUT_STACK_OFF 8388608ll
#define OUT_MASK_OFF  75497472ll

#define KST_SMEM 65536   // dynamic: old4 (32KB) + new4 (32KB)

__device__ float g_part[8ll * NTOK * 48];
__device__ float g_act[(size_t)NTOK * 48];
__device__ float g_k[(size_t)NUNIT * SDIM];
__device__ float g_mo[(size_t)NUNIT * SDIM];

__device__ __forceinline__ uint32_t smem_u32(const void* p) {
    uint32_t a;
    asm("{ .reg .u64 t; cvta.to.shared.u64 t, %1; cvt.u32.u64 %0, t; }"
        : "=r"(a) : "l"(p));
    return a;
}

// store float4 as two float2 into odd-stride smem (keeps LDG.128, STS 8B-aligned)
__device__ __forceinline__ void sts2x2(float* dst, float4 v) {
    *(float2*)dst       = make_float2(v.x, v.y);
    *(float2*)(dst + 2) = make_float2(v.z, v.w);
}

// ---- logits body: split-K 8, 64-tok tile, pad 66, float4 gmem loads.
__device__ __forceinline__ void logits_body(float* sm,
                                            const float* __restrict__ hid,
                                            const float* __restrict__ Wa,
                                            int blk) {
    float* a_sm = sm;            // 64 x 66
    float* w_sm = sm + 64 * 66;  // 48 x 66
    const int tile = blk >> 3;
    const int ks   = blk & 7;
    const int t0   = tile * 64;
    const int kb   = ks * 256;
    const int tid = threadIdx.x;
    const int tg  = tid & 15;
    const int og  = tid >> 4;
    float acc[4][3];
#pragma unroll
    for (int i = 0; i < 4; i++)
#pragma unroll
        for (int j = 0; j < 3; j++) acc[i][j] = 0.f;

    for (int kc = 0; kc < 256; kc += 64) {
        __syncthreads();
        for (int i = tid; i < 64 * 16; i += 256) {
            int t = i >> 4, c4 = (i & 15) << 2;
            float4 v = *(const float4*)&hid[(size_t)(t0 + t) * DMODEL + kb + kc + c4];
            sts2x2(&a_sm[t * 66 + c4], v);
        }
        for (int i = tid; i < 48 * 16; i += 256) {
            int o = i >> 4, c4 = (i & 15) << 2;
            float4 v = *(const float4*)&Wa[(size_t)o * DMODEL + kb + kc + c4];
            sts2x2(&w_sm[o * 66 + c4], v);
        }
        __syncthreads();
#pragma unroll
        for (int kk = 0; kk < 64; kk += 2) {
            float2 av[4], wv[3];
#pragma unroll
            for (int tt = 0; tt < 4; tt++)
                av[tt] = *(const float2*)&a_sm[(tg + 16 * tt) * 66 + kk];
#pragma unroll
            for (int oc = 0; oc < 3; oc++)
                wv[oc] = *(const float2*)&w_sm[(og * 3 + oc) * 66 + kk];
#pragma unroll
            for (int tt = 0; tt < 4; tt++)
#pragma unroll
                for (int oc = 0; oc < 3; oc++) {
                    acc[tt][oc] = fmaf(av[tt].x, wv[oc].x, acc[tt][oc]);
                    acc[tt][oc] = fmaf(av[tt].y, wv[oc].y, acc[tt][oc]);
                }
        }
    }
#pragma unroll
    for (int tt = 0; tt < 4; tt++)
#pragma unroll
        for (int oc = 0; oc < 3; oc++)
            g_part[((size_t)ks * NTOK + t0 + tg + 16 * tt) * 48 + og * 3 + oc] =
                acc[tt][oc];
}

// ---- down body: 128x64 tile, pad 34, float4 gmem loads.
__device__ __forceinline__ void down_body(float* sm,
                                          const float* __restrict__ hid,
                                          const float* __restrict__ Wd,
                                          int blk) {
    float* a_sm = sm;             // 128 x 34
    float* w_sm = sm + 128 * 34;  // 64 x 34
    const int u0 = blk * 128;
    const int tid = threadIdx.x;
    const int rg = tid & 15;
    const int cg = tid >> 4;
    float acc[8][4];
#pragma unroll
    for (int i = 0; i < 8; i++)
#pragma unroll
        for (int j = 0; j < 4; j++) acc[i][j] = 0.f;

    for (int kc = 0; kc < 128; kc += 32) {
        __syncthreads();
        for (int i = tid; i < 128 * 8; i += 256) {
            int r = i >> 3, c4 = (i & 7) << 2;
            float4 v = *(const float4*)&hid[(size_t)(u0 + r) * HDIM + kc + c4];
            sts2x2(&a_sm[r * 34 + c4], v);
        }
        for (int i = tid; i < 64 * 8; i += 256) {
            int c = i >> 3, c4 = (i & 7) << 2;
            float4 v = *(const float4*)&Wd[(size_t)c * HDIM + kc + c4];
            sts2x2(&w_sm[c * 34 + c4], v);
        }
        __syncthreads();
#pragma unroll
        for (int kk = 0; kk < 32; kk += 2) {
            float2 av[8], wv[4];
#pragma unroll
            for (int rr = 0; rr < 8; rr++)
                av[rr] = *(const float2*)&a_sm[(rg + 16 * rr) * 34 + kk];
#pragma unroll
            for (int cc = 0; cc < 4; cc++)
                wv[cc] = *(const float2*)&w_sm[(cg * 4 + cc) * 34 + kk];
#pragma unroll
            for (int rr = 0; rr < 8; rr++)
#pragma unroll
                for (int cc = 0; cc < 4; cc++) {
                    acc[rr][cc] = fmaf(av[rr].x, wv[cc].x, acc[rr][cc]);
                    acc[rr][cc] = fmaf(av[rr].y, wv[cc].y, acc[rr][cc]);
                }
        }
    }
#pragma unroll
    for (int rr = 0; rr < 8; rr++) {
        float4 v = make_float4(acc[rr][0], acc[rr][1], acc[rr][2], acc[rr][3]);
        *(float4*)&g_k[(size_t)(u0 + rg + 16 * rr) * SDIM + cg * 4] = v;
    }
}

// ---- Kernel 1: merged logits + down, reg-capped for 3 blocks/SM.
__global__ void __launch_bounds__(256, 3) k_proj(const float* __restrict__ hid,
                                                 const float* __restrict__ Wa,
                                                 const float* __restrict__ Wd) {
    __shared__ float sm[64 * 66 + 48 * 66];   // >= 128*34 + 64*34
    if (blockIdx.x < 512) logits_body(sm, hid, Wa, blockIdx.x);
    else                  down_body(sm, hid, Wd, blockIdx.x - 512);
}

// ---- Kernel 2: reduce partials, softmax over 3 actions.
__global__ void __launch_bounds__(256) k_actsm() {
    const int gid = blockIdx.x * 256 + threadIdx.x;
    const int t = gid >> 4, h = gid & 15;
    float l0 = 0.f, l1 = 0.f, l2 = 0.f;
#pragma unroll
    for (int ks = 0; ks < 8; ks++) {
        size_t b = ((size_t)ks * NTOK + t) * 48 + h * 3;
        l0 += g_part[b]; l1 += g_part[b + 1]; l2 += g_part[b + 2];
    }
    const float s = 0.08838834764831845f;
    l0 *= s; l1 *= s; l2 *= s;
    float m = fmaxf(l0, fmaxf(l1, l2));
    float e0 = __expf(l0 - m), e1 = __expf(l1 - m), e2 = __expf(l2 - m);
    float inv = 1.f / (e0 + e1 + e2);
    size_t ob = (size_t)t * 48 + h * 3;
    g_act[ob] = e0 * inv; g_act[ob + 1] = e1 * inv; g_act[ob + 2] = e2 * inv;
}

// ---- Kernel 3: stack blend, 8 units/block, 32KB TMA in/out, coef trick.
__global__ void __launch_bounds__(256) k_stack(const float* __restrict__ stk,
                                               const float* __restrict__ msk,
                                               const float* __restrict__ Wg,
                                               float* __restrict__ out) {
    extern __shared__ float4 dyn4[];
    float4* old4 = dyn4;             // [8][256]
    float4* new4 = dyn4 + 2048;      // [8][256]
    __shared__ alignas(8) unsigned long long mbar;
    __shared__ float4 ksm4[128];
    __shared__ float red[8][17];
    __shared__ float coef[8][17];
    __shared__ float msm[128];
    __shared__ float acts[24];
    const int tid  = threadIdx.x;
    const int slot = tid >> 4;
    const int dv   = tid & 15;
    const int u0   = blockIdx.x * 8;

    const uint32_t mb = smem_u32(&mbar);
    if (tid == 0) {
        asm volatile("mbarrier.init.shared.b64 [%0], 1;" :: "r"(mb) : "memory");
        asm volatile("fence.proxy.async.shared::cta;" ::: "memory");
    }
    __syncthreads();
    if (tid == 0) {
        asm volatile("mbarrier.arrive.expect_tx.shared.b64 _, [%0], 32768;"
                     :: "r"(mb) : "memory");
        asm volatile(
            "cp.async.bulk.shared::cluster.global.mbarrier::complete_tx::bytes "
            "[%0], [%1], 32768, [%2];"
            :: "r"(smem_u32(old4)),
               "l"(stk + (size_t)u0 * 1024), "r"(mb) : "memory");
    }

    const float4 g4 = ((const float4*)Wg)[dv];
    if (tid < 128) msm[tid] = msk[(size_t)u0 * 16 + tid];
    if (tid < 24) {
        int i = tid / 3, c = tid - i * 3;
        int u = u0 + i;
        acts[tid] = g_act[(size_t)(u >> 4) * 48 + (u & 15) * 3 + c];
    }
    if (tid < 128) {
        float4 kv = ((const float4*)g_k)[(size_t)u0 * 16 + tid];
        ksm4[tid] = kv;
        float p = kv.x * g4.x + kv.y * g4.y + kv.z * g4.z + kv.w * g4.w;
        p += __shfl_xor_sync(0xffffffffu, p, 8);
        p += __shfl_xor_sync(0xffffffffu, p, 4);
        p += __shfl_xor_sync(0xffffffffu, p, 2);
        p += __shfl_xor_sync(0xffffffffu, p, 1);
        if ((tid & 15) == 0) red[tid >> 4][16] = p;
    }

    {
        uint32_t done;
        asm volatile(
            "{\n\t.reg .pred p;\n\t"
            "WAITLP:\n\t"
            "mbarrier.try_wait.parity.shared.b64 p, [%1], 0, 0x989680;\n\t"
            "selp.b32 %0, 1, 0, p;\n\t"
            "@!p bra WAITLP;\n\t}"
            : "=r"(done) : "r"(mb) : "memory");
    }

    float4 r4[8];
#pragma unroll
    for (int i = 0; i < 8; i++) {
        r4[i] = old4[i * 256 + tid];
        float p = r4[i].x * g4.x + r4[i].y * g4.y + r4[i].z * g4.z + r4[i].w * g4.w;
        p += __shfl_xor_sync(0xffffffffu, p, 8);
        p += __shfl_xor_sync(0xffffffffu, p, 4);
        p += __shfl_xor_sync(0xffffffffu, p, 2);
        p += __shfl_xor_sync(0xffffffffu, p, 1);
        if (dv == 0) red[i][slot] = p;
    }
    __syncthreads();

#pragma unroll
    for (int i = 0; i < 8; i++) {
        float ap = acts[i * 3], apop = acts[i * 3 + 1], an = acts[i * 3 + 2];
        float4 prev = (slot == 0) ? ksm4[i * 16 + dv] : old4[i * 256 + tid - 16];
        float4 nxt  = (slot == 15) ? make_float4(0.f, 0.f, 0.f, 0.f)
                                   : old4[i * 256 + tid + 16];
        float4 c = r4[i];
        float4 nw;
        nw.x = ap * prev.x + apop * nxt.x + an * c.x;
        nw.y = ap * prev.y + apop * nxt.y + an * c.y;
        nw.z = ap * prev.z + apop * nxt.z + an * c.z;
        nw.w = ap * prev.w + apop * nxt.w + an * c.w;
        new4[i * 256 + tid] = nw;
    }

    if (tid < 128) {
        const int q2 = tid >> 4, j = tid & 15;
        float ap = acts[q2 * 3], apop = acts[q2 * 3 + 1], an = acts[q2 * 3 + 2];
        float pm = (j == 0) ? 1.f : msm[q2 * 16 + j - 1];
        float qm = (j < 15) ? msm[q2 * 16 + j + 1] : 0.f;
        out[OUT_MASK_OFF + (size_t)u0 * 16 + tid] =
            ap * pm + apop * qm + an * msm[q2 * 16 + j];
    }

    {
        const int q = tid >> 5;
        const int j = tid & 15;
        const int lane = tid & 31;
        float ap = acts[q * 3], apop = acts[q * 3 + 1], an = acts[q * 3 + 2];
        float pm = (j == 0) ? 1.f : msm[q * 16 + j - 1];
        float qm = (j < 15) ? msm[q * 16 + j + 1] : 0.f;
        float mk = ap * pm + apop * qm + an * msm[q * 16 + j];
        float Sm1 = (j == 0) ? red[q][16] : red[q][j - 1];
        float Sp1 = (j < 15) ? red[q][j + 1] : 0.f;
        float v = ap * Sm1 + apop * Sp1 + an * red[q][j] + (1.f - mk) * (-1e9f);
        float mx = v;
        mx = fmaxf(mx, __shfl_xor_sync(0xffffffffu, mx, 8));
        mx = fmaxf(mx, __shfl_xor_sync(0xffffffffu, mx, 4));
        mx = fmaxf(mx, __shfl_xor_sync(0xffffffffu, mx, 2));
        mx = fmaxf(mx, __shfl_xor_sync(0xffffffffu, mx, 1));
        float e = __expf(v - mx);
        float ss = e;
        ss += __shfl_xor_sync(0xffffffffu, ss, 8);
        ss += __shfl_xor_sync(0xffffffffu, ss, 4);
        ss += __shfl_xor_sync(0xffffffffu, ss, 2);
        ss += __shfl_xor_sync(0xffffffffu, ss, 1);
        float wgt = e / ss;
        float wp1 = __shfl_down_sync(0xffffffffu, wgt, 1);
        if (j == 15) wp1 = 0.f;
        float wm1 = __shfl_up_sync(0xffffffffu, wgt, 1);
        if (j == 0) wm1 = 0.f;
        if (lane < 16) {
            coef[q][j] = ap * wp1 + apop * wm1 + an * wgt;
            if (lane == 0) coef[q][16] = ap * wgt;
        }
    }
    __syncthreads();

    if (tid == 0) {
        asm volatile("fence.proxy.async.shared::cta;" ::: "memory");
        asm volatile(
            "cp.async.bulk.global.shared::cta.bulk_group [%0], [%1], 32768;"
            :: "l"(out + OUT_STACK_OFF + (size_t)u0 * 1024),
               "r"(smem_u32(new4)) : "memory");
        asm volatile("cp.async.bulk.commit_group;" ::: "memory");
    }

    {
        const int q = tid >> 5, d0 = tid & 31;
        const float* s  = (const float*)old4 + q * 1024;
        const float* ks = (const float*)ksm4 + q * 64;
#pragma unroll
        for (int dd = 0; dd < 2; dd++) {
            const int d = d0 + 32 * dd;
            float mo = coef[q][16] * ks[d];
#pragma unroll
            for (int m = 0; m < 16; m++) mo = fmaf(coef[q][m], s[m * 64 + d], mo);
            g_mo[(size_t)(u0 + q) * 64 + d] = mo;
        }
    }

    if (tid == 0)
        asm volatile("cp.async.bulk.wait_group 0;" ::: "memory");
}

// ---- Kernel 4: out = res_weight*(mo @ W_up^T)+hidden. Pad 66, float4 loads.
__global__ void __launch_bounds__(256, 3) k_up(const float* __restrict__ hid,
                                               const float* __restrict__ Wu,
                                               const float* __restrict__ rsw,
                                               float* __restrict__ out) {
    const int u0 = blockIdx.x * 64;
    __shared__ float a_sm[64 * 66];
    __shared__ float w_sm[128 * 66];
    const int tid = threadIdx.x;
    const int rg = tid & 15;
    const int cg = tid >> 4;

    for (int i = tid; i < 64 * 16; i += 256) {
        int r = i >> 4, c4 = (i & 15) << 2;
        float4 v = *(const float4*)&g_mo[(size_t)(u0 + r) * SDIM + c4];
        sts2x2(&a_sm[r * 66 + c4], v);
    }
    for (int i = tid; i < 128 * 16; i += 256) {
        int c = i >> 4, c4 = (i & 15) << 2;
        float4 v = *(const float4*)&Wu[(size_t)c * SDIM + c4];
        sts2x2(&w_sm[c * 66 + c4], v);
    }
    __syncthreads();

    float acc[4][8];
#pragma unroll
    for (int i = 0; i < 4; i++)
#pragma unroll
        for (int j = 0; j < 8; j++) acc[i][j] = 0.f;

#pragma unroll 4
    for (int kk = 0; kk < 64; kk += 2) {
        float2 av[4], wv[8];
#pragma unroll
        for (int rr = 0; rr < 4; rr++)
            av[rr] = *(const float2*)&a_sm[(rg + 16 * rr) * 66 + kk];
#pragma unroll
        for (int cc = 0; cc < 8; cc++)
            wv[cc] = *(const float2*)&w_sm[(cg * 8 + cc) * 66 + kk];
#pragma unroll
        for (int rr = 0; rr < 4; rr++)
#pragma unroll
            for (int cc = 0; cc < 8; cc++) {
                acc[rr][cc] = fmaf(av[rr].x, wv[cc].x, acc[rr][cc]);
                acc[rr][cc] = fmaf(av[rr].y, wv[cc].y, acc[rr][cc]);
            }
    }

    const float rw = rsw[0];
#pragma unroll
    for (int rr = 0; rr < 4; rr++) {
        size_t b = (size_t)(u0 + rg + 16 * rr) * HDIM + cg * 8;
        float4 h0 = *(const float4*)&hid[b];
        float4 h1 = *(const float4*)&hid[b + 4];
        float4 o0 = make_float4(fmaf(rw, acc[rr][0], h0.x), fmaf(rw, acc[rr][1], h0.y),
                                fmaf(rw, acc[rr][2], h0.z), fmaf(rw, acc[rr][3], h0.w));
        float4 o1 = make_float4(fmaf(rw, acc[rr][4], h1.x), fmaf(rw, acc[rr][5], h1.y),
                                fmaf(rw, acc[rr][6], h1.z), fmaf(rw, acc[rr][7], h1.w));
        *(float4*)&out[b] = o0;
        *(float4*)&out[b + 4] = o1;
    }
}

extern "C" void kernel_launch(void* const* d_in, const int* in_sizes, int n_in,
                              void* d_out, int out_size) {
    const float* hid = (const float*)d_in[0];
    const float* stk = (const float*)d_in[1];
    const float* msk = (const float*)d_in[2];
    const float* Wa  = (const float*)d_in[3];
    const float* Wg  = (const float*)d_in[4];
    const float* Wd  = (const float*)d_in[5];
    const float* Wu  = (const float*)d_in[6];
    const float* rsw = (const float*)d_in[7];
    float* out = (float*)d_out;

    cudaFuncSetAttribute(k_stack, cudaFuncAttributeMaxDynamicSharedMemorySize,
                         KST_SMEM);

    k_proj<<<1024, 256>>>(hid, Wa, Wd);
    k_actsm<<<256, 256>>>();
    k_stack<<<8192, 256, KST_SMEM>>>(stk, msk, Wg, out);
    k_up<<<1024, 256>>>(hid, Wu, rsw, out);
}

// round 17
// speedup vs baseline: 1.0681x; 1.0142x over previous
#include <cuda_runtime.h>
#include <cstdint>

#define NTOK   4096
#define DMODEL 2048
#define NH     16
#define HDIM   128
#define SDIM   64
#define NSLOT  16
#define NUNIT  (NTOK * NH)

#define OUT_STACK_OFF 8388608ll
#define OUT_MASK_OFF  75497472ll

#define KST_SMEM 65536

__device__ float g_part[8ll * NTOK * 48];
__device__ float g_act[(size_t)NTOK * 48];
__device__ float g_k[(size_t)NUNIT * SDIM];
__device__ float g_mo[(size_t)NUNIT * SDIM];

__device__ __forceinline__ uint32_t smem_u32(const void* p) {
    uint32_t a;
    asm("{ .reg .u64 t; cvta.to.shared.u64 t, %1; cvt.u32.u64 %0, t; }"
        : "=r"(a) : "l"(p));
    return a;
}

__device__ __forceinline__ void sts2x2(float* dst, float4 v) {
    *(float2*)dst       = make_float2(v.x, v.y);
    *(float2*)(dst + 2) = make_float2(v.z, v.w);
}

// ---- logits body: split-K 8, 64-tok tile, kc=32 chunks, pad 34.
__device__ __forceinline__ void logits_body(float* sm,
                                            const float* __restrict__ hid,
                                            const float* __restrict__ Wa,
                                            int blk) {
    float* a_sm = sm;            // 64 x 34
    float* w_sm = sm + 64 * 34;  // 48 x 34
    const int tile = blk >> 3;
    const int ks   = blk & 7;
    const int t0   = tile * 64;
    const int kb   = ks * 256;
    const int tid = threadIdx.x;
    const int tg  = tid & 15;
    const int og  = tid >> 4;
    float acc[4][3];
#pragma unroll
    for (int i = 0; i < 4; i++)
#pragma unroll
        for (int j = 0; j < 3; j++) acc[i][j] = 0.f;

    for (int kc = 0; kc < 256; kc += 32) {
        __syncthreads();
        for (int i = tid; i < 64 * 8; i += 256) {
            int t = i >> 3, c4 = (i & 7) << 2;
            float4 v = *(const float4*)&hid[(size_t)(t0 + t) * DMODEL + kb + kc + c4];
            sts2x2(&a_sm[t * 34 + c4], v);
        }
        for (int i = tid; i < 48 * 8; i += 256) {
            int o = i >> 3, c4 = (i & 7) << 2;
            float4 v = *(const float4*)&Wa[(size_t)o * DMODEL + kb + kc + c4];
            sts2x2(&w_sm[o * 34 + c4], v);
        }
        __syncthreads();
#pragma unroll
        for (int kk = 0; kk < 32; kk += 2) {
            float2 av[4], wv[3];
#pragma unroll
            for (int tt = 0; tt < 4; tt++)
                av[tt] = *(const float2*)&a_sm[(tg + 16 * tt) * 34 + kk];
#pragma unroll
            for (int oc = 0; oc < 3; oc++)
                wv[oc] = *(const float2*)&w_sm[(og * 3 + oc) * 34 + kk];
#pragma unroll
            for (int tt = 0; tt < 4; tt++)
#pragma unroll
                for (int oc = 0; oc < 3; oc++) {
                    acc[tt][oc] = fmaf(av[tt].x, wv[oc].x, acc[tt][oc]);
                    acc[tt][oc] = fmaf(av[tt].y, wv[oc].y, acc[tt][oc]);
                }
        }
    }
#pragma unroll
    for (int tt = 0; tt < 4; tt++)
#pragma unroll
        for (int oc = 0; oc < 3; oc++)
            g_part[((size_t)ks * NTOK + t0 + tg + 16 * tt) * 48 + og * 3 + oc] =
                acc[tt][oc];
}

// ---- down body: 64-row tile (1024 tiles), pad 34, frag 4x4.
__device__ __forceinline__ void down_body(float* sm,
                                          const float* __restrict__ hid,
                                          const float* __restrict__ Wd,
                                          int blk) {
    float* a_sm = sm;            // 64 x 34
    float* w_sm = sm + 64 * 34;  // 64 x 34
    const int u0 = blk * 64;
    const int tid = threadIdx.x;
    const int rg = tid & 15;
    const int cg = tid >> 4;
    float acc[4][4];
#pragma unroll
    for (int i = 0; i < 4; i++)
#pragma unroll
        for (int j = 0; j < 4; j++) acc[i][j] = 0.f;

    for (int kc = 0; kc < 128; kc += 32) {
        __syncthreads();
        for (int i = tid; i < 64 * 8; i += 256) {
            int r = i >> 3, c4 = (i & 7) << 2;
            float4 v = *(const float4*)&hid[(size_t)(u0 + r) * HDIM + kc + c4];
            sts2x2(&a_sm[r * 34 + c4], v);
        }
        for (int i = tid; i < 64 * 8; i += 256) {
            int c = i >> 3, c4 = (i & 7) << 2;
            float4 v = *(const float4*)&Wd[(size_t)c * HDIM + kc + c4];
            sts2x2(&w_sm[c * 34 + c4], v);
        }
        __syncthreads();
#pragma unroll
        for (int kk = 0; kk < 32; kk += 2) {
            float2 av[4], wv[4];
#pragma unroll
            for (int rr = 0; rr < 4; rr++)
                av[rr] = *(const float2*)&a_sm[(rg + 16 * rr) * 34 + kk];
#pragma unroll
            for (int cc = 0; cc < 4; cc++)
                wv[cc] = *(const float2*)&w_sm[(cg * 4 + cc) * 34 + kk];
#pragma unroll
            for (int rr = 0; rr < 4; rr++)
#pragma unroll
                for (int cc = 0; cc < 4; cc++) {
                    acc[rr][cc] = fmaf(av[rr].x, wv[cc].x, acc[rr][cc]);
                    acc[rr][cc] = fmaf(av[rr].y, wv[cc].y, acc[rr][cc]);
                }
        }
    }
#pragma unroll
    for (int rr = 0; rr < 4; rr++) {
        float4 v = make_float4(acc[rr][0], acc[rr][1], acc[rr][2], acc[rr][3]);
        *(float4*)&g_k[(size_t)(u0 + rg + 16 * rr) * SDIM + cg * 4] = v;
    }
}

// ---- Kernel 1: merged logits (512 blocks) + down (1024 blocks).
__global__ void __launch_bounds__(256, 4) k_proj(const float* __restrict__ hid,
                                                 const float* __restrict__ Wa,
                                                 const float* __restrict__ Wd) {
    __shared__ float sm[64 * 34 + 64 * 34];
    if (blockIdx.x < 512) logits_body(sm, hid, Wa, blockIdx.x);
    else                  down_body(sm, hid, Wd, blockIdx.x - 512);
}

// ---- Kernel 2: reduce partials, softmax over 3 actions.
__global__ void __launch_bounds__(256) k_actsm() {
    const int gid = blockIdx.x * 256 + threadIdx.x;
    const int t = gid >> 4, h = gid & 15;
    float l0 = 0.f, l1 = 0.f, l2 = 0.f;
#pragma unroll
    for (int ks = 0; ks < 8; ks++) {
        size_t b = ((size_t)ks * NTOK + t) * 48 + h * 3;
        l0 += g_part[b]; l1 += g_part[b + 1]; l2 += g_part[b + 2];
    }
    const float s = 0.08838834764831845f;
    l0 *= s; l1 *= s; l2 *= s;
    float m = fmaxf(l0, fmaxf(l1, l2));
    float e0 = __expf(l0 - m), e1 = __expf(l1 - m), e2 = __expf(l2 - m);
    float inv = 1.f / (e0 + e1 + e2);
    size_t ob = (size_t)t * 48 + h * 3;
    g_act[ob] = e0 * inv; g_act[ob + 1] = e1 * inv; g_act[ob + 2] = e2 * inv;
}

// ---- Kernel 3: stack blend, 8 units/block, 32KB TMA in/out, coef trick.
__global__ void __launch_bounds__(256) k_stack(const float* __restrict__ stk,
                                               const float* __restrict__ msk,
                                               const float* __restrict__ Wg,
                                               float* __restrict__ out) {
    extern __shared__ float4 dyn4[];
    float4* old4 = dyn4;
    float4* new4 = dyn4 + 2048;
    __shared__ alignas(8) unsigned long long mbar;
    __shared__ float4 ksm4[128];
    __shared__ float red[8][17];
    __shared__ float coef[8][17];
    __shared__ float msm[128];
    __shared__ float acts[24];
    const int tid  = threadIdx.x;
    const int slot = tid >> 4;
    const int dv   = tid & 15;
    const int u0   = blockIdx.x * 8;

    const uint32_t mb = smem_u32(&mbar);
    if (tid == 0) {
        asm volatile("mbarrier.init.shared.b64 [%0], 1;" :: "r"(mb) : "memory");
        asm volatile("fence.proxy.async.shared::cta;" ::: "memory");
    }
    __syncthreads();
    if (tid == 0) {
        asm volatile("mbarrier.arrive.expect_tx.shared.b64 _, [%0], 32768;"
                     :: "r"(mb) : "memory");
        asm volatile(
            "cp.async.bulk.shared::cluster.global.mbarrier::complete_tx::bytes "
            "[%0], [%1], 32768, [%2];"
            :: "r"(smem_u32(old4)),
               "l"(stk + (size_t)u0 * 1024), "r"(mb) : "memory");
    }

    const float4 g4 = ((const float4*)Wg)[dv];
    if (tid < 128) msm[tid] = msk[(size_t)u0 * 16 + tid];
    if (tid < 24) {
        int i = tid / 3, c = tid - i * 3;
        int u = u0 + i;
        acts[tid] = g_act[(size_t)(u >> 4) * 48 + (u & 15) * 3 + c];
    }
    if (tid < 128) {
        float4 kv = ((const float4*)g_k)[(size_t)u0 * 16 + tid];
        ksm4[tid] = kv;
        float p = kv.x * g4.x + kv.y * g4.y + kv.z * g4.z + kv.w * g4.w;
        p += __shfl_xor_sync(0xffffffffu, p, 8);
        p += __shfl_xor_sync(0xffffffffu, p, 4);
        p += __shfl_xor_sync(0xffffffffu, p, 2);
        p += __shfl_xor_sync(0xffffffffu, p, 1);
        if ((tid & 15) == 0) red[tid >> 4][16] = p;
    }

    {
        uint32_t done;
        asm volatile(
            "{\n\t.reg .pred p;\n\t"
            "WAITLP:\n\t"
            "mbarrier.try_wait.parity.shared.b64 p, [%1], 0, 0x989680;\n\t"
            "selp.b32 %0, 1, 0, p;\n\t"
            "@!p bra WAITLP;\n\t}"
            : "=r"(done) : "r"(mb) : "memory");
    }

    float4 r4[8];
#pragma unroll
    for (int i = 0; i < 8; i++) {
        r4[i] = old4[i * 256 + tid];
        float p = r4[i].x * g4.x + r4[i].y * g4.y + r4[i].z * g4.z + r4[i].w * g4.w;
        p += __shfl_xor_sync(0xffffffffu, p, 8);
        p += __shfl_xor_sync(0xffffffffu, p, 4);
        p += __shfl_xor_sync(0xffffffffu, p, 2);
        p += __shfl_xor_sync(0xffffffffu, p, 1);
        if (dv == 0) red[i][slot] = p;
    }
    __syncthreads();

#pragma unroll
    for (int i = 0; i < 8; i++) {
        float ap = acts[i * 3], apop = acts[i * 3 + 1], an = acts[i * 3 + 2];
        float4 prev = (slot == 0) ? ksm4[i * 16 + dv] : old4[i * 256 + tid - 16];
        float4 nxt  = (slot == 15) ? make_float4(0.f, 0.f, 0.f, 0.f)
                                   : old4[i * 256 + tid + 16];
        float4 c = r4[i];
        float4 nw;
        nw.x = ap * prev.x + apop * nxt.x + an * c.x;
        nw.y = ap * prev.y + apop * nxt.y + an * c.y;
        nw.z = ap * prev.z + apop * nxt.z + an * c.z;
        nw.w = ap * prev.w + apop * nxt.w + an * c.w;
        new4[i * 256 + tid] = nw;
    }

    if (tid < 128) {
        const int q2 = tid >> 4, j = tid & 15;
        float ap = acts[q2 * 3], apop = acts[q2 * 3 + 1], an = acts[q2 * 3 + 2];
        float pm = (j == 0) ? 1.f : msm[q2 * 16 + j - 1];
        float qm = (j < 15) ? msm[q2 * 16 + j + 1] : 0.f;
        out[OUT_MASK_OFF + (size_t)u0 * 16 + tid] =
            ap * pm + apop * qm + an * msm[q2 * 16 + j];
    }

    {
        const int q = tid >> 5;
        const int j = tid & 15;
        const int lane = tid & 31;
        float ap = acts[q * 3], apop = acts[q * 3 + 1], an = acts[q * 3 + 2];
        float pm = (j == 0) ? 1.f : msm[q * 16 + j - 1];
        float qm = (j < 15) ? msm[q * 16 + j + 1] : 0.f;
        float mk = ap * pm + apop * qm + an * msm[q * 16 + j];
        float Sm1 = (j == 0) ? red[q][16] : red[q][j - 1];
        float Sp1 = (j < 15) ? red[q][j + 1] : 0.f;
        float v = ap * Sm1 + apop * Sp1 + an * red[q][j] + (1.f - mk) * (-1e9f);
        float mx = v;
        mx = fmaxf(mx, __shfl_xor_sync(0xffffffffu, mx, 8));
        mx = fmaxf(mx, __shfl_xor_sync(0xffffffffu, mx, 4));
        mx = fmaxf(mx, __shfl_xor_sync(0xffffffffu, mx, 2));
        mx = fmaxf(mx, __shfl_xor_sync(0xffffffffu, mx, 1));
        float e = __expf(v - mx);
        float ss = e;
        ss += __shfl_xor_sync(0xffffffffu, ss, 8);
        ss += __shfl_xor_sync(0xffffffffu, ss, 4);
        ss += __shfl_xor_sync(0xffffffffu, ss, 2);
        ss += __shfl_xor_sync(0xffffffffu, ss, 1);
        float wgt = e / ss;
        float wp1 = __shfl_down_sync(0xffffffffu, wgt, 1);
        if (j == 15) wp1 = 0.f;
        float wm1 = __shfl_up_sync(0xffffffffu, wgt, 1);
        if (j == 0) wm1 = 0.f;
        if (lane < 16) {
            coef[q][j] = ap * wp1 + apop * wm1 + an * wgt;
            if (lane == 0) coef[q][16] = ap * wgt;
        }
    }
    __syncthreads();

    if (tid == 0) {
        asm volatile("fence.proxy.async.shared::cta;" ::: "memory");
        asm volatile(
            "cp.async.bulk.global.shared::cta.bulk_group [%0], [%1], 32768;"
            :: "l"(out + OUT_STACK_OFF + (size_t)u0 * 1024),
               "r"(smem_u32(new4)) : "memory");
        asm volatile("cp.async.bulk.commit_group;" ::: "memory");
    }

    {
        const int q = tid >> 5, d0 = tid & 31;
        const float* s  = (const float*)old4 + q * 1024;
        const float* ks = (const float*)ksm4 + q * 64;
#pragma unroll
        for (int dd = 0; dd < 2; dd++) {
            const int d = d0 + 32 * dd;
            float mo = coef[q][16] * ks[d];
#pragma unroll
            for (int m = 0; m < 16; m++) mo = fmaf(coef[q][m], s[m * 64 + d], mo);
            g_mo[(size_t)(u0 + q) * 64 + d] = mo;
        }
    }

    if (tid == 0)
        asm volatile("cp.async.bulk.wait_group 0;" ::: "memory");
}

// ---- Kernel 4: out = rw*(mo @ W_up^T)+hid. 64x64 tiles, 2048 blocks, 4x4 frag.
__global__ void __launch_bounds__(256, 4) k_up(const float* __restrict__ hid,
                                               const float* __restrict__ Wu,
                                               const float* __restrict__ rsw,
                                               float* __restrict__ out) {
    const int u0 = (blockIdx.x >> 1) * 64;
    const int ch = blockIdx.x & 1;          // col half: cols ch*64 .. +63
    __shared__ float a_sm[64 * 66];
    __shared__ float w_sm[64 * 66];
    const int tid = threadIdx.x;
    const int rg = tid & 15;                // rows rg + 16*rr (rr<4)
    const int cg = tid >> 4;                // cols ch*64 + cg*4 .. +3

    for (int i = tid; i < 64 * 16; i += 256) {
        int r = i >> 4, c4 = (i & 15) << 2;
        float4 v = *(const float4*)&g_mo[(size_t)(u0 + r) * SDIM + c4];
        sts2x2(&a_sm[r * 66 + c4], v);
    }
    for (int i = tid; i < 64 * 16; i += 256) {
        int c = i >> 4, c4 = (i & 15) << 2;
        float4 v = *(const float4*)&Wu[(size_t)(ch * 64 + c) * SDIM + c4];
        sts2x2(&w_sm[c * 66 + c4], v);
    }
    __syncthreads();

    float acc[4][4];
#pragma unroll
    for (int i = 0; i < 4; i++)
#pragma unroll
        for (int j = 0; j < 4; j++) acc[i][j] = 0.f;

#pragma unroll 4
    for (int kk = 0; kk < 64; kk += 2) {
        float2 av[4], wv[4];
#pragma unroll
        for (int rr = 0; rr < 4; rr++)
            av[rr] = *(const float2*)&a_sm[(rg + 16 * rr) * 66 + kk];
#pragma unroll
        for (int cc = 0; cc < 4; cc++)
            wv[cc] = *(const float2*)&w_sm[(cg * 4 + cc) * 66 + kk];
#pragma unroll
        for (int rr = 0; rr < 4; rr++)
#pragma unroll
            for (int cc = 0; cc < 4; cc++) {
                acc[rr][cc] = fmaf(av[rr].x, wv[cc].x, acc[rr][cc]);
                acc[rr][cc] = fmaf(av[rr].y, wv[cc].y, acc[rr][cc]);
            }
    }

    const float rw = rsw[0];
#pragma unroll
    for (int rr = 0; rr < 4; rr++) {
        size_t b = (size_t)(u0 + rg + 16 * rr) * HDIM + ch * 64 + cg * 4;
        float4 h0 = *(const float4*)&hid[b];
        float4 o0 = make_float4(fmaf(rw, acc[rr][0], h0.x), fmaf(rw, acc[rr][1], h0.y),
                                fmaf(rw, acc[rr][2], h0.z), fmaf(rw, acc[rr][3], h0.w));
        *(float4*)&out[b] = o0;
    }
}

extern "C" void kernel_launch(void* const* d_in, const int* in_sizes, int n_in,
                              void* d_out, int out_size) {
    const float* hid = (const float*)d_in[0];
    const float* stk = (const float*)d_in[1];
    const float* msk = (const float*)d_in[2];
    const float* Wa  = (const float*)d_in[3];
    const float* Wg  = (const float*)d_in[4];
    const float* Wd  = (const float*)d_in[5];
    const float* Wu  = (const float*)d_in[6];
    const float* rsw = (const float*)d_in[7];
    float* out = (float*)d_out;

    cudaFuncSetAttribute(k_stack, cudaFuncAttributeMaxDynamicSharedMemorySize,
                         KST_SMEM);

    k_proj<<<1536, 256>>>(hid, Wa, Wd);
    k_actsm<<<256, 256>>>();
    k_stack<<<8192, 256, KST_SMEM>>>(stk, msk, Wg, out);
    k_up<<<2048, 256>>>(hid, Wu, rsw, out);
}